// round 3
// baseline (speedup 1.0000x reference)
#include <cuda_runtime.h>
#include <cuda_bf16.h>
#include <math.h>

// ---------------- problem constants (fixed by the dataset) ----------------
#define NN   20000      // nodes
#define EE   320000     // edges
#define DIN  512
#define DH   256
#define GG   128        // graphs

// ---------------- static scratch (no runtime allocation allowed) ----------
__device__ int   d_counts[NN];
__device__ int   d_rowptr[NN + 1];
__device__ int   d_cursor[NN];
__device__ int   d_col[EE];
__device__ float d_dinv[NN];
__device__ float d_bufA[NN * DH];   // y = (X@W)*dinv
__device__ float d_bufB[NN * DH];   // h = relu(gather(y))
__device__ float d_psum[GG * DH];
__device__ float d_pcnt[GG];

// ---------------- init: zero counts + pooling accumulators ---------------
__global__ void init_kernel() {
    int i = blockIdx.x * blockDim.x + threadIdx.x;
    if (i < NN) d_counts[i] = 0;
    if (i < GG * DH) d_psum[i] = 0.f;
    if (i < GG) d_pcnt[i] = 0.f;
}

// ---------------- histogram of in-degrees (dst) ---------------------------
__global__ void hist_kernel(const int* __restrict__ dst) {
    int e = blockIdx.x * blockDim.x + threadIdx.x;
    if (e < EE) atomicAdd(&d_counts[dst[e]], 1);
}

// ---------------- single-block prefix scan -> rowptr/cursor/dinv ----------
__global__ void prefix_kernel() {
    __shared__ int ssum[1024];
    const int T = 1024;
    int t = threadIdx.x;
    const int per = (NN + T - 1) / T;          // 20
    int start = t * per;
    int end = min(start + per, NN);
    int s = 0;
    for (int i = start; i < end; i++) s += d_counts[i];
    ssum[t] = s;
    __syncthreads();
    // Hillis-Steele inclusive scan over 1024 partial sums
    for (int off = 1; off < T; off <<= 1) {
        int v = (t >= off) ? ssum[t - off] : 0;
        __syncthreads();
        ssum[t] += v;
        __syncthreads();
    }
    int run = (t == 0) ? 0 : ssum[t - 1];
    for (int i = start; i < end; i++) {
        d_rowptr[i] = run;
        d_cursor[i] = run;
        int c = d_counts[i];
        run += c;
        d_dinv[i] = rsqrtf((float)(c + 1));    // +1 self loop
    }
    if (t == T - 1) d_rowptr[NN] = ssum[T - 1];
}

// ---------------- CSR fill ------------------------------------------------
__global__ void fill_kernel(const int* __restrict__ src, const int* __restrict__ dst) {
    int e = blockIdx.x * blockDim.x + threadIdx.x;
    if (e < EE) {
        int p = atomicAdd(&d_cursor[dst[e]], 1);
        d_col[p] = src[e];
    }
}

// ---------------- fp32 SMEM-tiled GEMM: C[M,256] = A[M,K] @ B[K,256] ------
// epilogue: row-scale by dinv[row]
#define TM 64
#define TN 64
#define TK 16
__global__ void gemm_scale_kernel(const float* __restrict__ A,
                                  const float* __restrict__ B,
                                  float* __restrict__ C,
                                  int M, int K) {
    __shared__ float As[TK][TM + 1];
    __shared__ float Bs[TK][TN];
    int tx = threadIdx.x & 15;
    int ty = threadIdx.x >> 4;
    int blockRow = blockIdx.y * TM;
    int blockCol = blockIdx.x * TN;

    float acc[4][4];
#pragma unroll
    for (int i = 0; i < 4; i++)
#pragma unroll
        for (int j = 0; j < 4; j++) acc[i][j] = 0.f;

    for (int k0 = 0; k0 < K; k0 += TK) {
#pragma unroll
        for (int i = 0; i < 4; i++) {
            int idx = threadIdx.x + i * 256;           // 0..1023
            int m = idx >> 4, kk = idx & 15;
            int gr = blockRow + m;
            As[kk][m] = (gr < M) ? A[(size_t)gr * K + k0 + kk] : 0.f;
        }
#pragma unroll
        for (int i = 0; i < 4; i++) {
            int idx = threadIdx.x + i * 256;
            int kk = idx >> 6, n = idx & 63;
            Bs[kk][n] = B[(k0 + kk) * DH + blockCol + n];
        }
        __syncthreads();
#pragma unroll
        for (int kk = 0; kk < TK; kk++) {
            float a[4], b[4];
#pragma unroll
            for (int i = 0; i < 4; i++) a[i] = As[kk][ty * 4 + i];
#pragma unroll
            for (int j = 0; j < 4; j++) b[j] = Bs[kk][tx * 4 + j];
#pragma unroll
            for (int i = 0; i < 4; i++)
#pragma unroll
                for (int j = 0; j < 4; j++) acc[i][j] += a[i] * b[j];
        }
        __syncthreads();
    }
#pragma unroll
    for (int i = 0; i < 4; i++) {
        int gr = blockRow + ty * 4 + i;
        if (gr < M) {
            float s = d_dinv[gr];
#pragma unroll
            for (int j = 0; j < 4; j++)
                C[(size_t)gr * DH + blockCol + tx * 4 + j] = acc[i][j] * s;
        }
    }
}

// ---------------- warp-per-node CSR gather + bias + relu ------------------
__device__ __forceinline__ float4 f4add(float4 a, float4 b) {
    a.x += b.x; a.y += b.y; a.z += b.z; a.w += b.w; return a;
}

__global__ void gather_relu_kernel(const float* __restrict__ y,
                                   float* __restrict__ out,
                                   const float* __restrict__ bias) {
    int node = blockIdx.x * (blockDim.x >> 5) + (threadIdx.x >> 5);
    if (node >= NN) return;
    int lane = threadIdx.x & 31;
    const float4* yv = (const float4*)y;          // 64 float4 per row

    float4 a0 = yv[(size_t)node * 64 + lane];        // self loop (pre-scaled row)
    float4 a1 = yv[(size_t)node * 64 + 32 + lane];

    int beg = d_rowptr[node], end = d_rowptr[node + 1];
    for (int e = beg; e < end; e++) {
        int src = d_col[e];
        a0 = f4add(a0, yv[(size_t)src * 64 + lane]);
        a1 = f4add(a1, yv[(size_t)src * 64 + 32 + lane]);
    }
    float s = d_dinv[node];
    float4 b0 = ((const float4*)bias)[lane];
    float4 b1 = ((const float4*)bias)[32 + lane];
    float4 r0, r1;
    r0.x = fmaxf(fmaf(a0.x, s, b0.x), 0.f);
    r0.y = fmaxf(fmaf(a0.y, s, b0.y), 0.f);
    r0.z = fmaxf(fmaf(a0.z, s, b0.z), 0.f);
    r0.w = fmaxf(fmaf(a0.w, s, b0.w), 0.f);
    r1.x = fmaxf(fmaf(a1.x, s, b1.x), 0.f);
    r1.y = fmaxf(fmaf(a1.y, s, b1.y), 0.f);
    r1.z = fmaxf(fmaf(a1.z, s, b1.z), 0.f);
    r1.w = fmaxf(fmaf(a1.w, s, b1.w), 0.f);
    float4* ov = (float4*)out;
    ov[(size_t)node * 64 + lane] = r0;
    ov[(size_t)node * 64 + 32 + lane] = r1;
}

// ---------------- layer-2 gather fused with mean-pool accumulation -------
__global__ void gather_pool_kernel(const float* __restrict__ y,
                                   const float* __restrict__ bias,
                                   const int* __restrict__ batch) {
    int node = blockIdx.x * (blockDim.x >> 5) + (threadIdx.x >> 5);
    if (node >= NN) return;
    int lane = threadIdx.x & 31;
    const float4* yv = (const float4*)y;

    float4 a0 = yv[(size_t)node * 64 + lane];
    float4 a1 = yv[(size_t)node * 64 + 32 + lane];

    int beg = d_rowptr[node], end = d_rowptr[node + 1];
    for (int e = beg; e < end; e++) {
        int src = d_col[e];
        a0 = f4add(a0, yv[(size_t)src * 64 + lane]);
        a1 = f4add(a1, yv[(size_t)src * 64 + 32 + lane]);
    }
    float s = d_dinv[node];
    float4 b0 = ((const float4*)bias)[lane];
    float4 b1 = ((const float4*)bias)[32 + lane];

    float h[8];
    h[0] = fmaxf(fmaf(a0.x, s, b0.x), 0.f);
    h[1] = fmaxf(fmaf(a0.y, s, b0.y), 0.f);
    h[2] = fmaxf(fmaf(a0.z, s, b0.z), 0.f);
    h[3] = fmaxf(fmaf(a0.w, s, b0.w), 0.f);
    h[4] = fmaxf(fmaf(a1.x, s, b1.x), 0.f);
    h[5] = fmaxf(fmaf(a1.y, s, b1.y), 0.f);
    h[6] = fmaxf(fmaf(a1.z, s, b1.z), 0.f);
    h[7] = fmaxf(fmaf(a1.w, s, b1.w), 0.f);

    int g = batch[node];
    float* ps = &d_psum[g * DH];
#pragma unroll
    for (int c = 0; c < 4; c++) atomicAdd(&ps[lane * 4 + c], h[c]);
#pragma unroll
    for (int c = 0; c < 4; c++) atomicAdd(&ps[128 + lane * 4 + c], h[4 + c]);
    if (lane == 0) atomicAdd(&d_pcnt[g], 1.0f);
}

// ---------------- final: (psum/cnt) @ w_fc + b_fc -------------------------
__global__ void final_kernel(const float* __restrict__ wfc,
                             const float* __restrict__ bfc,
                             float* __restrict__ out) {
    int g = blockIdx.x;
    int lane = threadIdx.x;
    float acc = 0.f;
    for (int i = lane; i < DH; i += 32)
        acc += d_psum[g * DH + i] * wfc[i];
#pragma unroll
    for (int off = 16; off > 0; off >>= 1)
        acc += __shfl_down_sync(0xffffffffu, acc, off);
    if (lane == 0) {
        float c = fmaxf(d_pcnt[g], 1.0f);
        out[g] = acc / c + bfc[0];
    }
}

// ---------------- launch --------------------------------------------------
extern "C" void kernel_launch(void* const* d_in, const int* in_sizes, int n_in,
                              void* d_out, int out_size) {
    const float* x    = (const float*)d_in[0];
    const int*   ei   = (const int*)d_in[1];      // [2, E]: row0 src, row1 dst
    const int*   bat  = (const int*)d_in[2];
    const float* W1   = (const float*)d_in[3];
    const float* b1   = (const float*)d_in[4];
    const float* W2   = (const float*)d_in[5];
    const float* b2   = (const float*)d_in[6];
    const float* wfc  = (const float*)d_in[7];
    const float* bfc  = (const float*)d_in[8];
    float* out = (float*)d_out;

    const int* src = ei;
    const int* dst = ei + EE;

    // CSR build + dinv
    init_kernel<<<(GG * DH + 255) / 256, 256>>>();
    hist_kernel<<<(EE + 255) / 256, 256>>>(dst);
    prefix_kernel<<<1, 1024>>>();
    fill_kernel<<<(EE + 255) / 256, 256>>>(src, dst);

    dim3 gdim1(DH / TN, (NN + TM - 1) / TM);
    // layer 1: y1 = (x @ W1) * dinv
    gemm_scale_kernel<<<gdim1, 256>>>(x, W1, d_bufA, NN, DIN);
    // h1 = relu(gather(y1)*dinv + b1)
    gather_relu_kernel<<<(NN + 7) / 8, 256>>>(d_bufA, d_bufB, b1);
    // layer 2: y2 = (h1 @ W2) * dinv
    gemm_scale_kernel<<<gdim1, 256>>>(d_bufB, W2, d_bufA, NN, DH);
    // h2 = relu(gather(y2)*dinv + b2), fused mean-pool accumulation
    gather_pool_kernel<<<(NN + 7) / 8, 256>>>(d_bufA, b2, bat);
    // out[g] = (psum[g]/cnt[g]) . w_fc + b_fc
    final_kernel<<<GG, 32>>>(wfc, bfc, out);
}

// round 4
// speedup vs baseline: 1.0349x; 1.0349x over previous
#include <cuda_runtime.h>
#include <cuda_bf16.h>
#include <math.h>

// ---------------- problem constants (fixed by the dataset) ----------------
#define NN   20000      // nodes
#define EE   320000     // edges
#define DIN  512
#define DH   256
#define GG   128        // graphs

// ---------------- static scratch (no runtime allocation allowed) ----------
__device__ int   d_counts[NN];
__device__ int   d_rowptr[NN + 1];
__device__ int   d_cursor[NN];
__device__ int   d_col[EE];
__device__ float d_dinv[NN];
__device__ float d_bufA[NN * DH];   // y = (X@W)*dinv
__device__ float d_bufB[NN * DH];   // h = relu(gather(y))
__device__ float d_gsum[GG];        // per-graph sum of (h2 . w_fc)
__device__ float d_gcnt[GG];

// ---------------- init: zero counts + pooling accumulators ---------------
__global__ void init_kernel() {
    int i = blockIdx.x * blockDim.x + threadIdx.x;
    if (i < NN) d_counts[i] = 0;
    if (i < GG) { d_gsum[i] = 0.f; d_gcnt[i] = 0.f; }
}

// ---------------- histogram of in-degrees (dst) ---------------------------
__global__ void hist_kernel(const int* __restrict__ dst) {
    int e = blockIdx.x * blockDim.x + threadIdx.x;
    if (e < EE) atomicAdd(&d_counts[dst[e]], 1);
}

// ---------------- single-block prefix scan -> rowptr/cursor/dinv ----------
__global__ void prefix_kernel() {
    __shared__ int ssum[1024];
    const int T = 1024;
    int t = threadIdx.x;
    const int per = (NN + T - 1) / T;          // 20
    int start = t * per;
    int end = min(start + per, NN);
    int s = 0;
    for (int i = start; i < end; i++) s += d_counts[i];
    ssum[t] = s;
    __syncthreads();
    for (int off = 1; off < T; off <<= 1) {
        int v = (t >= off) ? ssum[t - off] : 0;
        __syncthreads();
        ssum[t] += v;
        __syncthreads();
    }
    int run = (t == 0) ? 0 : ssum[t - 1];
    for (int i = start; i < end; i++) {
        d_rowptr[i] = run;
        d_cursor[i] = run;
        int c = d_counts[i];
        run += c;
        d_dinv[i] = rsqrtf((float)(c + 1));    // +1 self loop
    }
    if (t == T - 1) d_rowptr[NN] = ssum[T - 1];
}

// ---------------- CSR fill ------------------------------------------------
__global__ void fill_kernel(const int* __restrict__ src, const int* __restrict__ dst) {
    int e = blockIdx.x * blockDim.x + threadIdx.x;
    if (e < EE) {
        int p = atomicAdd(&d_cursor[dst[e]], 1);
        d_col[p] = src[e];
    }
}

// ---------------- SGEMM 128x128x16, 8x8 per thread ------------------------
// C[M,256] = A[M,K] @ B[K,256], epilogue row-scale by dinv[row]
#define BM 128
#define BN 128
#define BK 16
#define ASTRIDE 132   // padded to break store bank conflicts, keeps 16B align
__global__ __launch_bounds__(256, 2)
void gemm_scale_kernel(const float* __restrict__ A,
                       const float* __restrict__ B,
                       float* __restrict__ C,
                       int M, int K) {
    __shared__ float As[BK][ASTRIDE];   // A transposed: As[k][m]
    __shared__ float Bs[BK][BN];

    const int t  = threadIdx.x;
    const int tx = t & 15;              // 0..15 -> 8 cols each
    const int ty = t >> 4;              // 0..15 -> 8 rows each
    const int rowBase = blockIdx.y * BM;
    const int colBase = blockIdx.x * BN;

    float acc[8][8];
#pragma unroll
    for (int i = 0; i < 8; i++)
#pragma unroll
        for (int j = 0; j < 8; j++) acc[i][j] = 0.f;

    // A-load mapping: 512 float4 per tile (128 rows x 4 float4)
    const int ar0 = t >> 2;            // row within tile for f = t
    const int ac0 = t & 3;             // float4 index within the 16-col slab
    // B-load mapping: 512 float4 per tile (16 rows x 32 float4)
    const int br0 = t >> 5;
    const int bc0 = t & 31;

    for (int k0 = 0; k0 < K; k0 += BK) {
        // ---- stage A (transposed) ----
#pragma unroll
        for (int i = 0; i < 2; i++) {
            int r  = ar0 + i * 64;
            int gr = rowBase + r;
            float4 v = make_float4(0.f, 0.f, 0.f, 0.f);
            if (gr < M)
                v = *(const float4*)(A + (size_t)gr * K + k0 + ac0 * 4);
            As[ac0 * 4 + 0][r] = v.x;
            As[ac0 * 4 + 1][r] = v.y;
            As[ac0 * 4 + 2][r] = v.z;
            As[ac0 * 4 + 3][r] = v.w;
        }
        // ---- stage B ----
#pragma unroll
        for (int i = 0; i < 2; i++) {
            int r = br0 + i * 8;
            float4 v = *(const float4*)(B + (size_t)(k0 + r) * DH + colBase + bc0 * 4);
            *(float4*)&Bs[r][bc0 * 4] = v;
        }
        __syncthreads();

#pragma unroll
        for (int kk = 0; kk < BK; kk++) {
            float a[8], b[8];
            *(float4*)&a[0] = *(const float4*)&As[kk][ty * 8];
            *(float4*)&a[4] = *(const float4*)&As[kk][ty * 8 + 4];
            *(float4*)&b[0] = *(const float4*)&Bs[kk][tx * 8];
            *(float4*)&b[4] = *(const float4*)&Bs[kk][tx * 8 + 4];
#pragma unroll
            for (int i = 0; i < 8; i++)
#pragma unroll
                for (int j = 0; j < 8; j++) acc[i][j] = fmaf(a[i], b[j], acc[i][j]);
        }
        __syncthreads();
    }

    // ---- epilogue: scale by dinv[row], vector stores ----
#pragma unroll
    for (int i = 0; i < 8; i++) {
        int gr = rowBase + ty * 8 + i;
        if (gr < M) {
            float s = d_dinv[gr];
            float4 v0, v1;
            v0.x = acc[i][0] * s; v0.y = acc[i][1] * s;
            v0.z = acc[i][2] * s; v0.w = acc[i][3] * s;
            v1.x = acc[i][4] * s; v1.y = acc[i][5] * s;
            v1.z = acc[i][6] * s; v1.w = acc[i][7] * s;
            float* cp = C + (size_t)gr * DH + colBase + tx * 8;
            *(float4*)cp       = v0;
            *(float4*)(cp + 4) = v1;
        }
    }
}

// ---------------- warp-per-node CSR gather + bias + relu ------------------
__device__ __forceinline__ float4 f4add(float4 a, float4 b) {
    a.x += b.x; a.y += b.y; a.z += b.z; a.w += b.w; return a;
}

__global__ void gather_relu_kernel(const float* __restrict__ y,
                                   float* __restrict__ out,
                                   const float* __restrict__ bias) {
    int node = blockIdx.x * (blockDim.x >> 5) + (threadIdx.x >> 5);
    if (node >= NN) return;
    int lane = threadIdx.x & 31;
    const float4* yv = (const float4*)y;          // 64 float4 per row

    float4 a0 = yv[(size_t)node * 64 + lane];     // self loop (pre-scaled row)
    float4 a1 = yv[(size_t)node * 64 + 32 + lane];
    float4 c0 = make_float4(0.f, 0.f, 0.f, 0.f);
    float4 c1 = make_float4(0.f, 0.f, 0.f, 0.f);

    int beg = d_rowptr[node], end = d_rowptr[node + 1];
    int e = beg;
    for (; e + 1 < end; e += 2) {                 // unroll x2: MLP 4
        int s0 = d_col[e], s1 = d_col[e + 1];
        float4 p0 = yv[(size_t)s0 * 64 + lane];
        float4 p1 = yv[(size_t)s0 * 64 + 32 + lane];
        float4 q0 = yv[(size_t)s1 * 64 + lane];
        float4 q1 = yv[(size_t)s1 * 64 + 32 + lane];
        a0 = f4add(a0, p0); a1 = f4add(a1, p1);
        c0 = f4add(c0, q0); c1 = f4add(c1, q1);
    }
    if (e < end) {
        int s0 = d_col[e];
        a0 = f4add(a0, yv[(size_t)s0 * 64 + lane]);
        a1 = f4add(a1, yv[(size_t)s0 * 64 + 32 + lane]);
    }
    a0 = f4add(a0, c0); a1 = f4add(a1, c1);

    float s = d_dinv[node];
    float4 b0 = ((const float4*)bias)[lane];
    float4 b1 = ((const float4*)bias)[32 + lane];
    float4 r0, r1;
    r0.x = fmaxf(fmaf(a0.x, s, b0.x), 0.f);
    r0.y = fmaxf(fmaf(a0.y, s, b0.y), 0.f);
    r0.z = fmaxf(fmaf(a0.z, s, b0.z), 0.f);
    r0.w = fmaxf(fmaf(a0.w, s, b0.w), 0.f);
    r1.x = fmaxf(fmaf(a1.x, s, b1.x), 0.f);
    r1.y = fmaxf(fmaf(a1.y, s, b1.y), 0.f);
    r1.z = fmaxf(fmaf(a1.z, s, b1.z), 0.f);
    r1.w = fmaxf(fmaf(a1.w, s, b1.w), 0.f);
    float4* ov = (float4*)out;
    ov[(size_t)node * 64 + lane] = r0;
    ov[(size_t)node * 64 + 32 + lane] = r1;
}

// ---- layer-2 gather, fused with w_fc dot + mean-pool (1 atomic/node) -----
// mean_n(relu(...)) @ w_fc == mean_n(relu(...) @ w_fc): fold fc before pool.
__global__ void gather_pool_kernel(const float* __restrict__ y,
                                   const float* __restrict__ bias,
                                   const int* __restrict__ batch,
                                   const float* __restrict__ wfc) {
    int node = blockIdx.x * (blockDim.x >> 5) + (threadIdx.x >> 5);
    if (node >= NN) return;
    int lane = threadIdx.x & 31;
    const float4* yv = (const float4*)y;

    float4 a0 = yv[(size_t)node * 64 + lane];
    float4 a1 = yv[(size_t)node * 64 + 32 + lane];
    float4 c0 = make_float4(0.f, 0.f, 0.f, 0.f);
    float4 c1 = make_float4(0.f, 0.f, 0.f, 0.f);

    int beg = d_rowptr[node], end = d_rowptr[node + 1];
    int e = beg;
    for (; e + 1 < end; e += 2) {
        int s0 = d_col[e], s1 = d_col[e + 1];
        float4 p0 = yv[(size_t)s0 * 64 + lane];
        float4 p1 = yv[(size_t)s0 * 64 + 32 + lane];
        float4 q0 = yv[(size_t)s1 * 64 + lane];
        float4 q1 = yv[(size_t)s1 * 64 + 32 + lane];
        a0 = f4add(a0, p0); a1 = f4add(a1, p1);
        c0 = f4add(c0, q0); c1 = f4add(c1, q1);
    }
    if (e < end) {
        int s0 = d_col[e];
        a0 = f4add(a0, yv[(size_t)s0 * 64 + lane]);
        a1 = f4add(a1, yv[(size_t)s0 * 64 + 32 + lane]);
    }
    a0 = f4add(a0, c0); a1 = f4add(a1, c1);

    float s = d_dinv[node];
    float4 b0 = ((const float4*)bias)[lane];
    float4 b1 = ((const float4*)bias)[32 + lane];
    float4 w0 = ((const float4*)wfc)[lane];
    float4 w1 = ((const float4*)wfc)[32 + lane];

    float dot = 0.f;
    dot += fmaxf(fmaf(a0.x, s, b0.x), 0.f) * w0.x;
    dot += fmaxf(fmaf(a0.y, s, b0.y), 0.f) * w0.y;
    dot += fmaxf(fmaf(a0.z, s, b0.z), 0.f) * w0.z;
    dot += fmaxf(fmaf(a0.w, s, b0.w), 0.f) * w0.w;
    dot += fmaxf(fmaf(a1.x, s, b1.x), 0.f) * w1.x;
    dot += fmaxf(fmaf(a1.y, s, b1.y), 0.f) * w1.y;
    dot += fmaxf(fmaf(a1.z, s, b1.z), 0.f) * w1.z;
    dot += fmaxf(fmaf(a1.w, s, b1.w), 0.f) * w1.w;

#pragma unroll
    for (int off = 16; off > 0; off >>= 1)
        dot += __shfl_down_sync(0xffffffffu, dot, off);

    if (lane == 0) {
        int g = batch[node];
        atomicAdd(&d_gsum[g], dot);
        atomicAdd(&d_gcnt[g], 1.0f);
    }
}

// ---------------- final: gsum/cnt + b_fc ----------------------------------
__global__ void final_kernel(const float* __restrict__ bfc,
                             float* __restrict__ out) {
    int g = threadIdx.x;
    if (g < GG) {
        float c = fmaxf(d_gcnt[g], 1.0f);
        out[g] = d_gsum[g] / c + bfc[0];
    }
}

// ---------------- launch --------------------------------------------------
extern "C" void kernel_launch(void* const* d_in, const int* in_sizes, int n_in,
                              void* d_out, int out_size) {
    const float* x    = (const float*)d_in[0];
    const int*   ei   = (const int*)d_in[1];      // [2, E]: row0 src, row1 dst
    const int*   bat  = (const int*)d_in[2];
    const float* W1   = (const float*)d_in[3];
    const float* b1   = (const float*)d_in[4];
    const float* W2   = (const float*)d_in[5];
    const float* b2   = (const float*)d_in[6];
    const float* wfc  = (const float*)d_in[7];
    const float* bfc  = (const float*)d_in[8];
    float* out = (float*)d_out;

    const int* src = ei;
    const int* dst = ei + EE;

    // CSR build + dinv
    init_kernel<<<(NN + 255) / 256, 256>>>();
    hist_kernel<<<(EE + 255) / 256, 256>>>(dst);
    prefix_kernel<<<1, 1024>>>();
    fill_kernel<<<(EE + 255) / 256, 256>>>(src, dst);

    dim3 gdim(DH / BN, (NN + BM - 1) / BM);       // (2, 157)
    // layer 1: y1 = (x @ W1) * dinv
    gemm_scale_kernel<<<gdim, 256>>>(x, W1, d_bufA, NN, DIN);
    // h1 = relu(gather(y1)*dinv + b1)
    gather_relu_kernel<<<(NN + 7) / 8, 256>>>(d_bufA, d_bufB, b1);
    // layer 2: y2 = (h1 @ W2) * dinv
    gemm_scale_kernel<<<gdim, 256>>>(d_bufB, W2, d_bufA, NN, DH);
    // fused: relu(gather(y2)*dinv + b2) . w_fc, accumulated per graph
    gather_pool_kernel<<<(NN + 7) / 8, 256>>>(d_bufA, b2, bat, wfc);
    // out[g] = gsum/cnt + b_fc
    final_kernel<<<1, GG>>>(bfc, out);
}